// round 6
// baseline (speedup 1.0000x reference)
#include <cuda_runtime.h>

// LocalCorrRatio, fully fused via shared-weight decomposition + readiness tickets.
// Block p: computes bin-sum partials for its patch's 8 sub-regions (split at
// local coord 4 -> {4,5}^3 blocks), finalizes the 2 shift-0 etas, publishes
// partials, then signals the 8 shifted patches it contributes to; the 8th
// contributor to a shifted patch computes that patch's 2 etas in-block.
// Last block (by arrival) reduces all 4000 etas. All counters self-reset.

#define NPATCH 1000
#define W3 729
#define DIM 90
#define KEXP2 (-1386.4299343f)   // -961 * log2(e)

__device__ float g_part[NPATCH * 8 * 4 * 32];   // [p][s][v][bin] v: SwA,SxA,SwB,SxB
__device__ float g_stats[NPATCH * 8 * 4];       // [p][s][{sumT,sumT2,sumP,sumP2}]
__device__ float g_eta[4 * NPATCH];
__device__ unsigned int g_ready[NPATCH];        // zero-init; reset by winners
__device__ unsigned int g_count = 0;

__constant__ int cBASE[8]  = {0, 64, 144, 224, 324, 404, 504, 604};
__constant__ int cSPLIT[8] = {64, 144, 224, 324, 404, 504, 604, 729};

__device__ __forceinline__ float ex2(float x) {
    float r; asm("ex2.approx.f32 %0, %1;" : "=f"(r) : "f"(x)); return r;
}

__device__ __forceinline__ void finalize_eta(int dir, int lane, float Sw, float Sx,
                                             float sT, float sT2, float sP, float sP2,
                                             float* dst) {
    float sx  = (dir == 0) ? sT  : sP;
    float sx2 = (dir == 0) ? sT2 : sP2;
    float mean = sx * (1.0f / (float)W3);
    float var  = (sx2 - sx * sx * (1.0f / (float)W3)) * (1.0f / (float)(W3 - 1));
    float mi = Sx / (Sw + 1e-5f);
    float dm = mi - mean;
    float num = Sw * dm * dm;
    float den = Sw;
    #pragma unroll
    for (int o = 16; o; o >>= 1) {
        num += __shfl_xor_sync(0xffffffffu, num, o);
        den += __shfl_xor_sync(0xffffffffu, den, o);
    }
    if (lane == 0) *dst = (num / den) / (var + 1e-5f);
}

__global__ __launch_bounds__(256) void lcr_kernel(const float* __restrict__ yt,
                                                  const float* __restrict__ yp,
                                                  float* __restrict__ out) {
    const int p = blockIdx.x;
    const int ph = p / 100;
    const int pw = (p / 10) % 10;
    const int pd = p % 10;

    __shared__ float ts[W3];
    __shared__ float ps[W3];
    __shared__ float part_a[8][4][32];
    __shared__ float part_b[8][4][32];
    __shared__ float stats_sm[8][4];
    __shared__ int s_win[8];
    __shared__ unsigned int s_islast;

    const int tid = threadIdx.x;
    const int warp = tid >> 5;
    const int lane = tid & 31;
    const float cb = (float)lane * (1.0f / 31.0f);

    // ---- Load patch into sub-region-major order ----
    for (int idx = tid; idx < W3; idx += 256) {
        int i = idx / 81;
        int r = idx - i * 81;
        int j = r / 9;
        int k = r - j * 9;
        int g = ((ph * 9 + i) * DIM + (pw * 9 + j)) * DIM + (pd * 9 + k);
        float tv = yt[g];
        float pv = yp[g];
        int sh = (i >= 4), sw_ = (j >= 4), sd_ = (k >= 4);
        int s = (sh << 2) | (sw_ << 1) | sd_;
        int ii = i - (sh ? 4 : 0);
        int jj = j - (sw_ ? 4 : 0);
        int kk = k - (sd_ ? 4 : 0);
        int nw = sw_ ? 5 : 4;
        int nd = sd_ ? 5 : 4;
        int dest = cBASE[s] + (ii * nw + jj) * nd + kk;
        ts[dest] = tv;
        ps[dest] = pv;
    }
    __syncthreads();

    // ---- Stats for sub-region s == warp ----
    {
        int b0 = cBASE[warp];
        int b1 = (warp < 7) ? cBASE[warp + 1] : W3;
        float sT = 0.f, sT2 = 0.f, sP = 0.f, sP2 = 0.f;
        for (int idx = b0 + lane; idx < b1; idx += 32) {
            float tv = ts[idx], pv = ps[idx];
            sT += tv;  sT2 = fmaf(tv, tv, sT2);
            sP += pv;  sP2 = fmaf(pv, pv, sP2);
        }
        #pragma unroll
        for (int o = 16; o; o >>= 1) {
            sT  += __shfl_xor_sync(0xffffffffu, sT,  o);
            sT2 += __shfl_xor_sync(0xffffffffu, sT2, o);
            sP  += __shfl_xor_sync(0xffffffffu, sP,  o);
            sP2 += __shfl_xor_sync(0xffffffffu, sP2, o);
        }
        if (lane == 0) {
            stats_sm[warp][0] = sT;  stats_sm[warp][1] = sT2;
            stats_sm[warp][2] = sP;  stats_sm[warp][3] = sP2;
        }
    }

    // ---- Bin sums: lane = bin; warp's 92-voxel range split at one static
    //      sub-region boundary into 2 segments ----
    {
        const int s1b = 92 * warp;
        const int s1e = cSPLIT[warp];
        float SwA = 0.f, SxA = 0.f, SwB = 0.f, SxB = 0.f;
        #pragma unroll 4
        for (int idx = s1b; idx < s1e; idx++) {
            float tv = ts[idx], pv = ps[idx];
            float dA = pv - cb;
            float dB = tv - cb;
            float wA = ex2(dA * (dA * KEXP2));
            float wB = ex2(dB * (dB * KEXP2));
            SwA += wA;  SxA = fmaf(wA, tv, SxA);
            SwB += wB;  SxB = fmaf(wB, pv, SxB);
        }
        part_a[warp][0][lane] = SwA;
        part_a[warp][1][lane] = SxA;
        part_a[warp][2][lane] = SwB;
        part_a[warp][3][lane] = SxB;

        if (warp < 7) {
            const int s2b = s1e;
            const int s2e = 92 * warp + 92;
            SwA = 0.f; SxA = 0.f; SwB = 0.f; SxB = 0.f;
            #pragma unroll 4
            for (int idx = s2b; idx < s2e; idx++) {
                float tv = ts[idx], pv = ps[idx];
                float dA = pv - cb;
                float dB = tv - cb;
                float wA = ex2(dA * (dA * KEXP2));
                float wB = ex2(dB * (dB * KEXP2));
                SwA += wA;  SxA = fmaf(wA, tv, SxA);
                SwB += wB;  SxB = fmaf(wB, pv, SxB);
            }
            part_b[warp + 1][0][lane] = SwA;
            part_b[warp + 1][1][lane] = SxA;
            part_b[warp + 1][2][lane] = SwB;
            part_b[warp + 1][3][lane] = SxB;
        }
    }
    __syncthreads();

    // ---- Combine per sub-region, publish to gmem ----
    {
        const int s = warp;
        float v0 = part_a[s][0][lane];
        float v1 = part_a[s][1][lane];
        float v2 = part_a[s][2][lane];
        float v3 = part_a[s][3][lane];
        if (s >= 1) {
            v0 += part_b[s][0][lane];
            v1 += part_b[s][1][lane];
            v2 += part_b[s][2][lane];
            v3 += part_b[s][3][lane];
        }
        part_a[s][0][lane] = v0;
        part_a[s][1][lane] = v1;
        part_a[s][2][lane] = v2;
        part_a[s][3][lane] = v3;
        int gb = ((p * 8 + s) * 4) * 32 + lane;
        g_part[gb]      = v0;
        g_part[gb + 32] = v1;
        g_part[gb + 64] = v2;
        g_part[gb + 96] = v3;
        if (lane < 4) g_stats[(p * 8 + s) * 4 + lane] = stats_sm[s][lane];
    }
    __threadfence();       // publish this thread's partial/stat stores
    __syncthreads();

    // ---- Signal the 8 shifted patches this block contributes to ----
    if (tid < 8) {
        int s = tid;
        int cc = 7 - s;
        int dh = (cc >> 2) & 1, dw = (cc >> 1) & 1, dd = cc & 1;
        int pa = ph - dh; if (pa < 0) pa += 10;
        int pb = pw - dw; if (pb < 0) pb += 10;
        int pc = pd - dd; if (pc < 0) pc += 10;
        int pt = (pa * 10 + pb) * 10 + pc;
        unsigned int old = atomicAdd(&g_ready[pt], 1u);
        s_win[tid] = (old == 7u) ? pt : -1;
    }

    // ---- Shift-0 etas (variants 0 and 1) in parallel with the signaling ----
    if (warp < 2) {
        const int v0 = warp * 2;
        float Sw = 0.f, Sx = 0.f;
        #pragma unroll
        for (int s = 0; s < 8; s++) { Sw += part_a[s][v0][lane]; Sx += part_a[s][v0 + 1][lane]; }
        float sT = 0.f, sT2 = 0.f, sP = 0.f, sP2 = 0.f;
        #pragma unroll
        for (int s = 0; s < 8; s++) {
            sT += stats_sm[s][0]; sT2 += stats_sm[s][1];
            sP += stats_sm[s][2]; sP2 += stats_sm[s][3];
        }
        finalize_eta(warp, lane, Sw, Sx, sT, sT2, sP, sP2,
                     &g_eta[warp * NPATCH + p]);
    }
    __syncthreads();
    __threadfence();   // acquire: partials of other blocks now safe to read

    // ---- Gather etas for any shifted patches this block completed ----
    #pragma unroll 1
    for (int i = 0; i < 8; i++) {
        int pt = s_win[i];
        if (pt < 0) continue;
        if (warp < 2) {
            int a = pt / 100, b = (pt / 10) % 10, c = pt % 10;
            float Sw = 0.f, Sx = 0.f;
            float sT = 0.f, sT2 = 0.f, sP = 0.f, sP2 = 0.f;
            #pragma unroll
            for (int cc = 0; cc < 8; cc++) {
                int dh = (cc >> 2) & 1, dw = (cc >> 1) & 1, dd = cc & 1;
                int qa = a + dh; if (qa >= 10) qa -= 10;
                int qb = b + dw; if (qb >= 10) qb -= 10;
                int qc = c + dd; if (qc >= 10) qc -= 10;
                int q = (qa * 10 + qb) * 10 + qc;
                int s = 7 - cc;
                int gb = ((q * 8 + s) * 4 + warp * 2) * 32;
                Sw += g_part[gb + lane];
                Sx += g_part[gb + 32 + lane];
                int sb = (q * 8 + s) * 4;
                sT  += g_stats[sb + 0];
                sT2 += g_stats[sb + 1];
                sP  += g_stats[sb + 2];
                sP2 += g_stats[sb + 3];
            }
            finalize_eta(warp, lane, Sw, Sx, sT, sT2, sP, sP2,
                         &g_eta[(2 + warp) * NPATCH + pt]);
        }
        if (tid == 0) g_ready[pt] = 0;   // reset for next graph replay
    }

    // ---- Final reduction: last block by arrival ----
    __threadfence();   // publish eta writes (each writer thread fences)
    __syncthreads();
    if (tid == 0) {
        unsigned int old = atomicAdd(&g_count, 1u);
        s_islast = (old == NPATCH - 1) ? 1u : 0u;
    }
    __syncthreads();
    if (s_islast) {
        __threadfence();
        __shared__ double sh[256];
        double s = 0.0;
        for (int i = tid; i < 4 * NPATCH; i += 256) s += (double)g_eta[i];
        sh[tid] = s;
        __syncthreads();
        #pragma unroll
        for (int o = 128; o; o >>= 1) {
            if (tid < o) sh[tid] += sh[tid + o];
            __syncthreads();
        }
        if (tid == 0) {
            out[0] = (float)(-sh[0] / 12000.0);
            g_count = 0;
        }
    }
}

extern "C" void kernel_launch(void* const* d_in, const int* in_sizes, int n_in,
                              void* d_out, int out_size) {
    const float* y_true = (const float*)d_in[0];
    const float* y_pred = (const float*)d_in[1];
    float* out = (float*)d_out;
    lcr_kernel<<<NPATCH, 256>>>(y_true, y_pred, out);
}

// round 7
// speedup vs baseline: 1.3393x; 1.3393x over previous
#include <cuda_runtime.h>

// LocalCorrRatio via shared-weight decomposition (two kernels, R5 structure).
// Kernel 1 (unchanged from R5): block = shift-0 patch; per-sub-region bin
// partials ({4,5}^3 split at local coord 4), finalizes 2 shift-0 etas,
// publishes partials + stats.
// Kernel 2 (reworked): 125 blocks x 256; warp = one shifted patch, gathers its
// 8 contributors' partials for BOTH swap directions, finalizes 2 etas.
// Last block (125 arrivals) reduces all 4000 etas.

#define NPATCH 1000
#define W3 729
#define DIM 90
#define KEXP2 (-1386.4299343f)   // -961 * log2(e)

__device__ float g_part[NPATCH * 8 * 4 * 32];   // [p][s][v][bin] v: SwA,SxA,SwB,SxB
__device__ float g_stats[NPATCH * 8 * 4];       // [p][s][{sumT,sumT2,sumP,sumP2}]
__device__ float g_eta[4 * NPATCH];
__device__ unsigned int g_count = 0;

__constant__ int cBASE[8]  = {0, 64, 144, 224, 324, 404, 504, 604};
__constant__ int cSPLIT[8] = {64, 144, 224, 324, 404, 504, 604, 729};

__device__ __forceinline__ float ex2(float x) {
    float r; asm("ex2.approx.f32 %0, %1;" : "=f"(r) : "f"(x)); return r;
}

__device__ __forceinline__ void finalize_eta(int dir, int lane, float Sw, float Sx,
                                             float sT, float sT2, float sP, float sP2,
                                             float* dst) {
    float sx  = (dir == 0) ? sT  : sP;
    float sx2 = (dir == 0) ? sT2 : sP2;
    float mean = sx * (1.0f / (float)W3);
    float var  = (sx2 - sx * sx * (1.0f / (float)W3)) * (1.0f / (float)(W3 - 1));
    float mi = Sx / (Sw + 1e-5f);
    float dm = mi - mean;
    float num = Sw * dm * dm;
    float den = Sw;
    #pragma unroll
    for (int o = 16; o; o >>= 1) {
        num += __shfl_xor_sync(0xffffffffu, num, o);
        den += __shfl_xor_sync(0xffffffffu, den, o);
    }
    if (lane == 0) *dst = (num / den) / (var + 1e-5f);
}

__global__ __launch_bounds__(256) void lcr_part_kernel(const float* __restrict__ yt,
                                                       const float* __restrict__ yp) {
    const int p = blockIdx.x;
    const int ph = p / 100;
    const int pw = (p / 10) % 10;
    const int pd = p % 10;

    __shared__ float ts[W3];
    __shared__ float ps[W3];
    __shared__ float part_a[8][4][32];
    __shared__ float part_b[8][4][32];
    __shared__ float stats_sm[8][4];

    const int tid = threadIdx.x;
    const int warp = tid >> 5;
    const int lane = tid & 31;
    const float cb = (float)lane * (1.0f / 31.0f);

    // ---- Load patch into sub-region-major order ----
    for (int idx = tid; idx < W3; idx += 256) {
        int i = idx / 81;
        int r = idx - i * 81;
        int j = r / 9;
        int k = r - j * 9;
        int g = ((ph * 9 + i) * DIM + (pw * 9 + j)) * DIM + (pd * 9 + k);
        float tv = yt[g];
        float pv = yp[g];
        int sh = (i >= 4), sw_ = (j >= 4), sd_ = (k >= 4);
        int s = (sh << 2) | (sw_ << 1) | sd_;
        int ii = i - (sh ? 4 : 0);
        int jj = j - (sw_ ? 4 : 0);
        int kk = k - (sd_ ? 4 : 0);
        int nw = sw_ ? 5 : 4;
        int nd = sd_ ? 5 : 4;
        int dest = cBASE[s] + (ii * nw + jj) * nd + kk;
        ts[dest] = tv;
        ps[dest] = pv;
    }
    __syncthreads();

    // ---- Stats for sub-region s == warp ----
    {
        int b0 = cBASE[warp];
        int b1 = (warp < 7) ? cBASE[warp + 1] : W3;
        float sT = 0.f, sT2 = 0.f, sP = 0.f, sP2 = 0.f;
        for (int idx = b0 + lane; idx < b1; idx += 32) {
            float tv = ts[idx], pv = ps[idx];
            sT += tv;  sT2 = fmaf(tv, tv, sT2);
            sP += pv;  sP2 = fmaf(pv, pv, sP2);
        }
        #pragma unroll
        for (int o = 16; o; o >>= 1) {
            sT  += __shfl_xor_sync(0xffffffffu, sT,  o);
            sT2 += __shfl_xor_sync(0xffffffffu, sT2, o);
            sP  += __shfl_xor_sync(0xffffffffu, sP,  o);
            sP2 += __shfl_xor_sync(0xffffffffu, sP2, o);
        }
        if (lane == 0) {
            stats_sm[warp][0] = sT;  stats_sm[warp][1] = sT2;
            stats_sm[warp][2] = sP;  stats_sm[warp][3] = sP2;
        }
    }

    // ---- Bin sums: lane = bin; warp's 92-voxel range split at one static
    //      sub-region boundary into 2 segments ----
    {
        const int s1b = 92 * warp;
        const int s1e = cSPLIT[warp];
        float SwA = 0.f, SxA = 0.f, SwB = 0.f, SxB = 0.f;
        #pragma unroll 4
        for (int idx = s1b; idx < s1e; idx++) {
            float tv = ts[idx], pv = ps[idx];
            float dA = pv - cb;
            float dB = tv - cb;
            float wA = ex2(dA * (dA * KEXP2));
            float wB = ex2(dB * (dB * KEXP2));
            SwA += wA;  SxA = fmaf(wA, tv, SxA);
            SwB += wB;  SxB = fmaf(wB, pv, SxB);
        }
        part_a[warp][0][lane] = SwA;
        part_a[warp][1][lane] = SxA;
        part_a[warp][2][lane] = SwB;
        part_a[warp][3][lane] = SxB;

        if (warp < 7) {
            const int s2b = s1e;
            const int s2e = 92 * warp + 92;
            SwA = 0.f; SxA = 0.f; SwB = 0.f; SxB = 0.f;
            #pragma unroll 4
            for (int idx = s2b; idx < s2e; idx++) {
                float tv = ts[idx], pv = ps[idx];
                float dA = pv - cb;
                float dB = tv - cb;
                float wA = ex2(dA * (dA * KEXP2));
                float wB = ex2(dB * (dB * KEXP2));
                SwA += wA;  SxA = fmaf(wA, tv, SxA);
                SwB += wB;  SxB = fmaf(wB, pv, SxB);
            }
            part_b[warp + 1][0][lane] = SwA;
            part_b[warp + 1][1][lane] = SxA;
            part_b[warp + 1][2][lane] = SwB;
            part_b[warp + 1][3][lane] = SxB;
        }
    }
    __syncthreads();

    // ---- Combine per sub-region, publish to gmem ----
    {
        const int s = warp;
        float v0 = part_a[s][0][lane];
        float v1 = part_a[s][1][lane];
        float v2 = part_a[s][2][lane];
        float v3 = part_a[s][3][lane];
        if (s >= 1) {
            v0 += part_b[s][0][lane];
            v1 += part_b[s][1][lane];
            v2 += part_b[s][2][lane];
            v3 += part_b[s][3][lane];
        }
        part_a[s][0][lane] = v0;
        part_a[s][1][lane] = v1;
        part_a[s][2][lane] = v2;
        part_a[s][3][lane] = v3;
        int gb = ((p * 8 + s) * 4) * 32 + lane;
        g_part[gb]      = v0;
        g_part[gb + 32] = v1;
        g_part[gb + 64] = v2;
        g_part[gb + 96] = v3;
        if (lane < 4) g_stats[(p * 8 + s) * 4 + lane] = stats_sm[s][lane];
    }
    __syncthreads();

    // ---- Shift-0 etas (variants 0 and 1) ----
    if (warp < 2) {
        const int v0 = warp * 2;
        float Sw = 0.f, Sx = 0.f;
        #pragma unroll
        for (int s = 0; s < 8; s++) { Sw += part_a[s][v0][lane]; Sx += part_a[s][v0 + 1][lane]; }
        float sT = 0.f, sT2 = 0.f, sP = 0.f, sP2 = 0.f;
        #pragma unroll
        for (int s = 0; s < 8; s++) {
            sT += stats_sm[s][0]; sT2 += stats_sm[s][1];
            sP += stats_sm[s][2]; sP2 += stats_sm[s][3];
        }
        finalize_eta(warp, lane, Sw, Sx, sT, sT2, sP, sP2,
                     &g_eta[warp * NPATCH + p]);
    }
}

__global__ __launch_bounds__(256) void lcr_final_kernel(float* __restrict__ out) {
    const int tid = threadIdx.x;
    const int warp = tid >> 5;
    const int lane = tid & 31;
    const int pt = blockIdx.x * 8 + warp;        // 125 blocks x 8 warps = 1000
    const int a = pt / 100;
    const int b = (pt / 10) % 10;
    const int c = pt % 10;

    __shared__ unsigned int s_islast;

    float SwA = 0.f, SxA = 0.f, SwB = 0.f, SxB = 0.f;
    float sT = 0.f, sT2 = 0.f, sP = 0.f, sP2 = 0.f;
    #pragma unroll
    for (int cc = 0; cc < 8; cc++) {
        int dh = (cc >> 2) & 1, dw = (cc >> 1) & 1, dd = cc & 1;
        int qa = a + dh; if (qa >= 10) qa -= 10;
        int qb = b + dw; if (qb >= 10) qb -= 10;
        int qc = c + dd; if (qc >= 10) qc -= 10;
        int q = (qa * 10 + qb) * 10 + qc;
        int s = 7 - cc;                 // delta=0 -> hi half, delta=1 -> lo half
        int gb = ((q * 8 + s) * 4) * 32;
        SwA += g_part[gb + lane];
        SxA += g_part[gb + 32 + lane];
        SwB += g_part[gb + 64 + lane];
        SxB += g_part[gb + 96 + lane];
        int sb = (q * 8 + s) * 4;
        sT  += g_stats[sb + 0];
        sT2 += g_stats[sb + 1];
        sP  += g_stats[sb + 2];
        sP2 += g_stats[sb + 3];
    }
    finalize_eta(0, lane, SwA, SxA, sT, sT2, sP, sP2, &g_eta[2 * NPATCH + pt]);
    finalize_eta(1, lane, SwB, SxB, sT, sT2, sP, sP2, &g_eta[3 * NPATCH + pt]);

    // ---- Last block (by arrival) reduces all 4000 etas ----
    __threadfence();
    __syncthreads();
    if (tid == 0) {
        unsigned int old = atomicAdd(&g_count, 1u);
        s_islast = (old == 125 - 1) ? 1u : 0u;
    }
    __syncthreads();
    if (s_islast) {
        __threadfence();
        __shared__ double sh[256];
        double s = 0.0;
        for (int i = tid; i < 4 * NPATCH; i += 256) s += (double)g_eta[i];
        sh[tid] = s;
        __syncthreads();
        #pragma unroll
        for (int o = 128; o; o >>= 1) {
            if (tid < o) sh[tid] += sh[tid + o];
            __syncthreads();
        }
        if (tid == 0) {
            out[0] = (float)(-sh[0] / 12000.0);
            g_count = 0;
        }
    }
}

extern "C" void kernel_launch(void* const* d_in, const int* in_sizes, int n_in,
                              void* d_out, int out_size) {
    const float* y_true = (const float*)d_in[0];
    const float* y_pred = (const float*)d_in[1];
    float* out = (float*)d_out;
    lcr_part_kernel<<<NPATCH, 256>>>(y_true, y_pred);
    lcr_final_kernel<<<125, 256>>>(out);
}